// round 14
// baseline (speedup 1.0000x reference)
#include <cuda_runtime.h>
#include <cuda_fp16.h>
#include <math.h>
#include <stdint.h>

#define NN   50000
#define EE   800000
#define E2V  (EE + NN)
#define F1   256
#define OUTC 40
#define SB   512
#define NBLK ((NN + SB - 1) / SB)

// ---- scratch ----
__device__ __half g_h16  [(size_t)NN * F1];  // GEMM output / aggregation source (fp16)
__device__ __half g_out16[(size_t)NN * F1];  // aggregation output / next GEMM A (fp16)
__device__ float  g_asrc[NN * 8];
__device__ float  g_adst[NN * 8];
__device__ int    g_deg [NN];
__device__ int    g_rows[NN + 1];
__device__ int    g_cur [NN];
__device__ int    g_colsrc[E2V];
__device__ int    g_bsum[NBLK + 1];
__device__ float  g_gmax[3][16];

// ===========================================================================
__device__ __forceinline__ void atomicMaxF(float* addr, float val)
{
    unsigned int u = __float_as_uint(val);
    if (u >> 31) atomicMin((unsigned int*)addr, u);
    else         atomicMax((int*)addr, (int)u);
}

// ===========================================================================
// CSR build
// ===========================================================================
__global__ void init_deg_k()
{
    int i = blockIdx.x * blockDim.x + threadIdx.x;
    if (i < NN) g_deg[i] = 1;
    if (i < 48) ((float*)g_gmax)[i] = __int_as_float(0xFF800000);
}

__global__ void count_k(const int* __restrict__ dst)
{
    int e = blockIdx.x * blockDim.x + threadIdx.x;
    if (e < EE) atomicAdd(&g_deg[dst[e]], 1);
}

__global__ void scan1_k()
{
    __shared__ int sh[SB];
    int i = blockIdx.x * SB + threadIdx.x;
    sh[threadIdx.x] = (i < NN) ? g_deg[i] : 0;
    __syncthreads();
    #pragma unroll
    for (int o = 1; o < SB; o <<= 1) {
        int t = (threadIdx.x >= o) ? sh[threadIdx.x - o] : 0;
        __syncthreads();
        sh[threadIdx.x] += t;
        __syncthreads();
    }
    if (i < NN) g_rows[i + 1] = sh[threadIdx.x];
    if (threadIdx.x == SB - 1) g_bsum[blockIdx.x] = sh[SB - 1];
}

__global__ void scan2_k()
{
    __shared__ int sh[128];
    int t = threadIdx.x;
    int v = (t < NBLK) ? g_bsum[t] : 0;
    sh[t] = v;
    __syncthreads();
    #pragma unroll
    for (int o = 1; o < 128; o <<= 1) {
        int u = (t >= o) ? sh[t - o] : 0;
        __syncthreads();
        sh[t] += u;
        __syncthreads();
    }
    if (t < NBLK) g_bsum[t] = sh[t] - v;
}

__global__ void scan3_k()
{
    int i = blockIdx.x * blockDim.x + threadIdx.x;
    if (i >= NN) return;
    int end = g_rows[i + 1] + g_bsum[i / SB];
    g_rows[i + 1] = end;
    g_cur[i] = end - g_deg[i];
    if (i == 0) g_rows[0] = 0;
}

__global__ void scatter_k(const int* __restrict__ src, const int* __restrict__ dst)
{
    int e = blockIdx.x * blockDim.x + threadIdx.x;
    if (e >= E2V) return;
    int s, d;
    if (e < EE) { s = src[e]; d = dst[e]; } else { s = d = e - EE; }
    int pos = atomicAdd(&g_cur[d], 1);
    g_colsrc[pos] = s;
}

// ===========================================================================
// Attention dot products (fp16 h) + per-head global max  (R9-proven)
// ===========================================================================
template<int H>
__global__ void __launch_bounds__(256) dots_k(const float* __restrict__ att_s,
                                              const float* __restrict__ att_d,
                                              int C, int layer)
{
    __shared__ float rs[256], rd[256];
    int tid = threadIdx.x;
    int i = blockIdx.x * blockDim.x + tid;
    float s = -INFINITY, d = -INFINITY;
    if (i < NN * H) {
        int n = i / H, hh = i % H;
        const __half2* hp = (const __half2*)(g_h16 + (size_t)n * H * C + hh * C);
        const float* as = att_s + hh * C;
        const float* ad = att_d + hh * C;
        float ss = 0.f, dd = 0.f;
        for (int c = 0; c < C / 2; c++) {
            float2 v = __half22float2(__ldg(&hp[c]));
            ss = fmaf(v.x, as[2 * c], ss);
            ss = fmaf(v.y, as[2 * c + 1], ss);
            dd = fmaf(v.x, ad[2 * c], dd);
            dd = fmaf(v.y, ad[2 * c + 1], dd);
        }
        g_asrc[i] = ss;
        g_adst[i] = dd;
        s = ss; d = dd;
    }
    rs[tid] = s; rd[tid] = d;
    __syncthreads();
    #pragma unroll
    for (int o = 128; o >= H; o >>= 1) {
        if (tid < o) {
            rs[tid] = fmaxf(rs[tid], rs[tid + o]);
            rd[tid] = fmaxf(rd[tid], rd[tid + o]);
        }
        __syncthreads();
    }
    if (tid < H) {
        atomicMaxF(&g_gmax[layer][tid], rs[tid]);
        atomicMaxF(&g_gmax[layer][8 + tid], rd[tid]);
    }
}

// ===========================================================================
// SINGLE-PASS fused softmax + aggregation (R9-proven), fp16 in, fp16 out
// ===========================================================================
__global__ void __launch_bounds__(256) gat_fused8_k(const float* __restrict__ bias,
                                                    int relu, int layer)
{
    __shared__ float sex[8][32];
    __shared__ int   ssrc[8][4];

    int w = (blockIdx.x * blockDim.x + threadIdx.x) >> 5;
    int lane = threadIdx.x & 31;
    int wl = (threadIdx.x >> 5);
    if (w >= NN) return;
    int d = w;
    int beg = g_rows[d], end = g_rows[d + 1];

    int hsel  = lane & 7;
    int eslot = lane >> 3;
    int hi    = lane >> 4;

    float adh = __ldg(&g_adst[d * 8 + hsel]);
    float bh  = g_gmax[layer][hsel] + g_gmax[layer][8 + hsel];
    float bndh = bh > 0.f ? bh : 0.2f * bh;

    float2 acc2[4];
    #pragma unroll
    for (int i = 0; i < 4; i++) acc2[i] = make_float2(0.f, 0.f);
    float smpart = 0.f;

    int p0 = beg;
    int nfull = (end - beg) >> 2;
    for (int ch = 0; ch < nfull; ch++, p0 += 4) {
        int s = __ldg(&g_colsrc[p0 + eslot]);
        float e = __ldg(&g_asrc[s * 8 + hsel]) + adh;
        e = e > 0.f ? e : 0.2f * e;
        float ex = __expf(e - bndh);
        smpart += ex;
        sex[wl][lane] = ex;
        if (hsel == 0) ssrc[wl][eslot] = s;
        __syncwarp();
        #pragma unroll
        for (int e4 = 0; e4 < 4; e4++) {
            int se = ssrc[wl][e4];
            const __half2* hp = (const __half2*)(g_h16 + (size_t)se * F1);
            #pragma unroll
            for (int i = 0; i < 4; i++) {
                float wgt = sex[wl][e4 * 8 + 2 * i + hi];
                float2 f = __half22float2(__ldg(&hp[i * 32 + lane]));
                acc2[i].x = fmaf(wgt, f.x, acc2[i].x);
                acc2[i].y = fmaf(wgt, f.y, acc2[i].y);
            }
        }
        __syncwarp();
    }
    int rem = end - p0;
    if (rem > 0) {
        float ex = 0.f;
        int s = 0;
        if (eslot < rem) {
            s = __ldg(&g_colsrc[p0 + eslot]);
            float e = __ldg(&g_asrc[s * 8 + hsel]) + adh;
            e = e > 0.f ? e : 0.2f * e;
            ex = __expf(e - bndh);
            smpart += ex;
        }
        sex[wl][lane] = ex;
        if (hsel == 0 && eslot < rem) ssrc[wl][eslot] = s;
        __syncwarp();
        for (int e4 = 0; e4 < rem; e4++) {
            int se = ssrc[wl][e4];
            const __half2* hp = (const __half2*)(g_h16 + (size_t)se * F1);
            #pragma unroll
            for (int i = 0; i < 4; i++) {
                float wgt = sex[wl][e4 * 8 + 2 * i + hi];
                float2 f = __half22float2(__ldg(&hp[i * 32 + lane]));
                acc2[i].x = fmaf(wgt, f.x, acc2[i].x);
                acc2[i].y = fmaf(wgt, f.y, acc2[i].y);
            }
        }
        __syncwarp();
    }

    smpart += __shfl_xor_sync(0xffffffffu, smpart, 8);
    smpart += __shfl_xor_sync(0xffffffffu, smpart, 16);
    float invl = 1.f / (smpart + 1e-16f);

    __half* op = g_out16 + (size_t)d * F1;
    int c0 = (lane & 15) * 2;
    #pragma unroll
    for (int i = 0; i < 4; i++) {
        int head = 2 * i + hi;
        float inv = __shfl_sync(0xffffffffu, invl, head);
        float v0 = acc2[i].x * inv + bias[head * 32 + c0];
        float v1 = acc2[i].y * inv + bias[head * 32 + c0 + 1];
        if (relu) { v0 = fmaxf(v0, 0.f); v1 = fmaxf(v1, 0.f); }
        *(__half2*)&op[head * 32 + c0] = __floats2half2_rn(v0, v1);
    }
}

// ===========================================================================
// SINGLE-PASS fused layer-3 (R9-proven)
// ===========================================================================
__global__ void __launch_bounds__(256) gat_fused1_k(const float* __restrict__ bias,
                                                    float* __restrict__ out, int layer)
{
    __shared__ float sex[8][32];
    __shared__ int   ssrc[8][32];

    int w = (blockIdx.x * blockDim.x + threadIdx.x) >> 5;
    int lane = threadIdx.x & 31;
    int wl = (threadIdx.x >> 5);
    if (w >= NN) return;
    int d = w;
    int beg = g_rows[d], end = g_rows[d + 1];
    float add = g_adst[d];
    float b = g_gmax[layer][0] + g_gmax[layer][8];
    float bnd = b > 0.f ? b : 0.2f * b;

    float a0 = 0.f, a1 = 0.f, smpart = 0.f;

    for (int p0 = beg; p0 < end; p0 += 32) {
        int ne = min(32, end - p0);
        float ex = 0.f;
        int s = 0;
        if (lane < ne) {
            s = __ldg(&g_colsrc[p0 + lane]);
            float e = __ldg(&g_asrc[s]) + add;
            e = e > 0.f ? e : 0.2f * e;
            ex = __expf(e - bnd);
            smpart += ex;
        }
        sex[wl][lane] = ex;
        ssrc[wl][lane] = s;
        __syncwarp();
        for (int e = 0; e < ne; e++) {
            int se = ssrc[wl][e];
            float al = sex[wl][e];
            const __half* hp = g_h16 + (size_t)se * OUTC;
            a0 = fmaf(al, __half2float(__ldg(&hp[lane])), a0);
            if (lane < 8) a1 = fmaf(al, __half2float(__ldg(&hp[lane + 32])), a1);
        }
        __syncwarp();
    }
    #pragma unroll
    for (int o = 16; o; o >>= 1) smpart += __shfl_xor_sync(0xffffffffu, smpart, o);
    float inv = 1.f / (smpart + 1e-16f);

    float v0 = a0 * inv + bias[lane];
    float v1 = (lane < 8) ? a1 * inv + bias[lane + 32] : -INFINITY;
    float m = fmaxf(v0, v1);
    #pragma unroll
    for (int o = 16; o; o >>= 1) m = fmaxf(m, __shfl_xor_sync(0xffffffffu, m, o));
    float s2 = __expf(v0 - m) + ((lane < 8) ? __expf(v1 - m) : 0.f);
    #pragma unroll
    for (int o = 16; o; o >>= 1) s2 += __shfl_xor_sync(0xffffffffu, s2, o);
    float lg = m + logf(s2);
    out[(size_t)d * OUTC + lane] = v0 - lg;
    if (lane < 8) out[(size_t)d * OUTC + lane + 32] = v1 - lg;
}

// ===========================================================================
// Common GEMM pieces (R9-proven tf32 MMA inner loop)
// ===========================================================================
#define GBM 128
#define GBN 64
#define GBK 16
#define AS_STRIDE 20
#define BS_STRIDE 72

__device__ __forceinline__ void cp16(uint32_t dst, const void* src, int valid)
{
    asm volatile("cp.async.ca.shared.global [%0], [%1], 16, %2;\n"
                 :: "r"(dst), "l"(src), "r"(valid ? 16 : 0));
}

__device__ __forceinline__ void mma1688(float* c, const uint32_t* a, const uint32_t* b)
{
    asm volatile(
        "mma.sync.aligned.m16n8k8.row.col.f32.tf32.tf32.f32 "
        "{%0,%1,%2,%3},{%4,%5,%6,%7},{%8,%9},{%0,%1,%2,%3};"
        : "+f"(c[0]), "+f"(c[1]), "+f"(c[2]), "+f"(c[3])
        : "r"(a[0]), "r"(a[1]), "r"(a[2]), "r"(a[3]), "r"(b[0]), "r"(b[1]));
}

// ===========================================================================
// TF32 GEMM, fp32 A (layer 1, R9 verbatim): g_h16 = A[M,K] @ B[K,Ncol]
// ===========================================================================
__global__ void __launch_bounds__(256) tf32gemm_k(const float* __restrict__ A,
                                                  const float* __restrict__ B,
                                                  int M, int Ncol, int K)
{
    __shared__ float As[2][GBM * AS_STRIDE];
    __shared__ float Bs[2][GBK * BS_STRIDE];

    int tid  = threadIdx.x;
    int warp = tid >> 5;
    int lane = tid & 31;
    int wm = warp >> 1;
    int wn = warp & 1;
    int bm = blockIdx.y * GBM;
    int bn = blockIdx.x * GBN;
    int lr = lane >> 2;
    int lc = lane & 3;

    int ar0 = tid >> 2;
    int ac  = (tid & 3) * 4;
    int br  = tid >> 4;
    int bc  = (tid & 15) * 4;

    uint32_t as_base = (uint32_t)__cvta_generic_to_shared(&As[0][0]);
    uint32_t bs_base = (uint32_t)__cvta_generic_to_shared(&Bs[0][0]);
    const uint32_t AS_BYTES = GBM * AS_STRIDE * 4;
    const uint32_t BS_BYTES = GBK * BS_STRIDE * 4;

    int niter = K / GBK;

    {
        #pragma unroll
        for (int i = 0; i < 2; i++) {
            int r = ar0 + i * 64;
            int gr = bm + r;
            int ok = gr < M;
            const float* src = A + (size_t)(ok ? gr : 0) * K + ac;
            cp16(as_base + (r * AS_STRIDE + ac) * 4, src, ok);
        }
        {
            int gc = bn + bc;
            int ok = gc < Ncol;
            const float* src = B + (size_t)br * Ncol + (ok ? gc : 0);
            cp16(bs_base + (br * BS_STRIDE + bc) * 4, src, ok);
        }
        asm volatile("cp.async.commit_group;\n" ::);
    }

    float c[2][4][4];
    #pragma unroll
    for (int i = 0; i < 2; i++)
        #pragma unroll
        for (int j = 0; j < 4; j++)
            #pragma unroll
            for (int r = 0; r < 4; r++) c[i][j][r] = 0.f;

    int buf = 0;
    for (int it = 0; it < niter; it++) {
        int has_next = (it + 1 < niter);
        if (has_next) {
            int k0 = (it + 1) * GBK;
            uint32_t ab = as_base + (buf ^ 1) * AS_BYTES;
            uint32_t bb = bs_base + (buf ^ 1) * BS_BYTES;
            #pragma unroll
            for (int i = 0; i < 2; i++) {
                int r = ar0 + i * 64;
                int gr = bm + r;
                int ok = gr < M;
                const float* src = A + (size_t)(ok ? gr : 0) * K + k0 + ac;
                cp16(ab + (r * AS_STRIDE + ac) * 4, src, ok);
            }
            {
                int gc = bn + bc;
                int ok = gc < Ncol;
                const float* src = B + (size_t)(k0 + br) * Ncol + (ok ? gc : 0);
                cp16(bb + (br * BS_STRIDE + bc) * 4, src, ok);
            }
            asm volatile("cp.async.commit_group;\n" ::);
            asm volatile("cp.async.wait_group 1;\n" ::);
        } else {
            asm volatile("cp.async.wait_group 0;\n" ::);
        }
        __syncthreads();

        const float* Asb = As[buf];
        const float* Bsb = Bs[buf];
        #pragma unroll
        for (int kk = 0; kk < GBK; kk += 8) {
            uint32_t afrag[2][4], bfrag[4][2];
            #pragma unroll
            for (int i = 0; i < 2; i++) {
                int rb = wm * 32 + i * 16;
                afrag[i][0] = __float_as_uint(Asb[(rb + lr)     * AS_STRIDE + kk + lc]);
                afrag[i][1] = __float_as_uint(Asb[(rb + 8 + lr) * AS_STRIDE + kk + lc]);
                afrag[i][2] = __float_as_uint(Asb[(rb + lr)     * AS_STRIDE + kk + 4 + lc]);
                afrag[i][3] = __float_as_uint(Asb[(rb + 8 + lr) * AS_STRIDE + kk + 4 + lc]);
            }
            #pragma unroll
            for (int j = 0; j < 4; j++) {
                int nb = wn * 32 + j * 8;
                bfrag[j][0] = __float_as_uint(Bsb[(kk + lc)     * BS_STRIDE + nb + lr]);
                bfrag[j][1] = __float_as_uint(Bsb[(kk + 4 + lc) * BS_STRIDE + nb + lr]);
            }
            #pragma unroll
            for (int i = 0; i < 2; i++)
                #pragma unroll
                for (int j = 0; j < 4; j++)
                    mma1688(c[i][j], afrag[i], bfrag[j]);
        }
        __syncthreads();
        buf ^= 1;
    }

    #pragma unroll
    for (int i = 0; i < 2; i++) {
        int r0 = bm + wm * 32 + i * 16 + lr;
        #pragma unroll
        for (int j = 0; j < 4; j++) {
            int col = bn + wn * 32 + j * 8 + lc * 2;
            if (col < Ncol) {
                if (r0 < M)
                    *(__half2*)&g_h16[(size_t)r0 * Ncol + col] =
                        __floats2half2_rn(c[i][j][0], c[i][j][1]);
                if (r0 + 8 < M)
                    *(__half2*)&g_h16[(size_t)(r0 + 8) * Ncol + col] =
                        __floats2half2_rn(c[i][j][2], c[i][j][3]);
            }
        }
    }
}

// ===========================================================================
// TF32 GEMM, fp16 A (layers 2-3): A = g_out16. A tile loaded via LDG.128
// (8 halves/thread), register-prefetched, converted to fp32 at SMEM fill.
// B path + MMA inner loop identical to the proven kernel.
// ===========================================================================
__global__ void __launch_bounds__(256) tf32gemm_f16a_k(const float* __restrict__ B,
                                                       int M, int Ncol, int K)
{
    const __half* A = g_out16;
    __shared__ float As[2][GBM * AS_STRIDE];
    __shared__ float Bs[2][GBK * BS_STRIDE];

    int tid  = threadIdx.x;
    int warp = tid >> 5;
    int lane = tid & 31;
    int wm = warp >> 1;
    int wn = warp & 1;
    int bm = blockIdx.y * GBM;
    int bn = blockIdx.x * GBN;
    int lr = lane >> 2;
    int lc = lane & 3;

    // A-load coords: 128 rows x 16 halves per stage; 2 threads/row, 8 halves each
    int arow = tid >> 1;           // 0..127
    int ac8  = (tid & 1) * 8;      // 0 or 8
    int agr  = bm + arow;
    int aok  = agr < M;
    const __half* aptr = A + (size_t)(aok ? agr : 0) * K + ac8;

    int br  = tid >> 4;
    int bc  = (tid & 15) * 4;

    uint32_t bs_base = (uint32_t)__cvta_generic_to_shared(&Bs[0][0]);
    const uint32_t BS_BYTES = GBK * BS_STRIDE * 4;

    int niter = K / GBK;

    // prologue: A tile 0 -> regs; B tile 0 -> cp.async
    uint4 areg = aok ? __ldg((const uint4*)aptr) : make_uint4(0, 0, 0, 0);
    {
        int gc = bn + bc;
        int ok = gc < Ncol;
        const float* src = B + (size_t)br * Ncol + (ok ? gc : 0);
        cp16(bs_base + (br * BS_STRIDE + bc) * 4, src, ok);
        asm volatile("cp.async.commit_group;\n" ::);
    }

    float c[2][4][4];
    #pragma unroll
    for (int i = 0; i < 2; i++)
        #pragma unroll
        for (int j = 0; j < 4; j++)
            #pragma unroll
            for (int r = 0; r < 4; r++) c[i][j][r] = 0.f;

    int buf = 0;
    for (int it = 0; it < niter; it++) {
        // store current A regs (convert h2 -> f32) into As[buf]
        {
            float2 f0 = __half22float2(*(__half2*)&areg.x);
            float2 f1 = __half22float2(*(__half2*)&areg.y);
            float2 f2 = __half22float2(*(__half2*)&areg.z);
            float2 f3 = __half22float2(*(__half2*)&areg.w);
            float* dst = &As[buf][arow * AS_STRIDE + ac8];
            *(float4*)dst       = make_float4(f0.x, f0.y, f1.x, f1.y);
            *(float4*)(dst + 4) = make_float4(f2.x, f2.y, f3.x, f3.y);
        }
        int has_next = (it + 1 < niter);
        if (has_next) {
            int k0 = (it + 1) * GBK;
            // prefetch next A tile into regs (overlaps with MMA below)
            areg = aok ? __ldg((const uint4*)(aptr + k0)) : make_uint4(0, 0, 0, 0);
            // next B tile via cp.async
            uint32_t bb = bs_base + (buf ^ 1) * BS_BYTES;
            int gc = bn + bc;
            int ok = gc < Ncol;
            const float* src = B + (size_t)(k0 + br) * Ncol + (ok ? gc : 0);
            cp16(bb + (br * BS_STRIDE + bc) * 4, src, ok);
            asm volatile("cp.async.commit_group;\n" ::);
            asm volatile("cp.async.wait_group 1;\n" ::);
        } else {
            asm volatile("cp.async.wait_group 0;\n" ::);
        }
        __syncthreads();

        const float* Asb = As[buf];
        const float* Bsb = Bs[buf];
        #pragma unroll
        for (int kk = 0; kk < GBK; kk += 8) {
            uint32_t afrag[2][4], bfrag[4][2];
            #pragma unroll
            for (int i = 0; i < 2; i++) {
                int rb = wm * 32 + i * 16;
                afrag[i][0] = __float_as_uint(Asb[(rb + lr)     * AS_STRIDE + kk + lc]);
                afrag[i][1] = __float_as_uint(Asb[(rb + 8 + lr) * AS_STRIDE + kk + lc]);
                afrag[i][2] = __float_as_uint(Asb[(rb + lr)     * AS_STRIDE + kk + 4 + lc]);
                afrag[i][3] = __float_as_uint(Asb[(rb + 8 + lr) * AS_STRIDE + kk + 4 + lc]);
            }
            #pragma unroll
            for (int j = 0; j < 4; j++) {
                int nb = wn * 32 + j * 8;
                bfrag[j][0] = __float_as_uint(Bsb[(kk + lc)     * BS_STRIDE + nb + lr]);
                bfrag[j][1] = __float_as_uint(Bsb[(kk + 4 + lc) * BS_STRIDE + nb + lr]);
            }
            #pragma unroll
            for (int i = 0; i < 2; i++)
                #pragma unroll
                for (int j = 0; j < 4; j++)
                    mma1688(c[i][j], afrag[i], bfrag[j]);
        }
        __syncthreads();
        buf ^= 1;
    }

    #pragma unroll
    for (int i = 0; i < 2; i++) {
        int r0 = bm + wm * 32 + i * 16 + lr;
        #pragma unroll
        for (int j = 0; j < 4; j++) {
            int col = bn + wn * 32 + j * 8 + lc * 2;
            if (col < Ncol) {
                if (r0 < M)
                    *(__half2*)&g_h16[(size_t)r0 * Ncol + col] =
                        __floats2half2_rn(c[i][j][0], c[i][j][1]);
                if (r0 + 8 < M)
                    *(__half2*)&g_h16[(size_t)(r0 + 8) * Ncol + col] =
                        __floats2half2_rn(c[i][j][2], c[i][j][3]);
            }
        }
    }
}

// ===========================================================================
// Launcher
// ===========================================================================
extern "C" void kernel_launch(void* const* d_in, const int* in_sizes, int n_in,
                              void* d_out, int out_size)
{
    const float* x    = (const float*)d_in[0];
    const int*   ei   = (const int*)  d_in[1];
    const int*   srcv = ei;
    const int*   dstv = ei + EE;
    const float* W1  = (const float*)d_in[2];
    const float* as1 = (const float*)d_in[3];
    const float* ad1 = (const float*)d_in[4];
    const float* b1  = (const float*)d_in[5];
    const float* W2  = (const float*)d_in[6];
    const float* as2 = (const float*)d_in[7];
    const float* ad2 = (const float*)d_in[8];
    const float* b2  = (const float*)d_in[9];
    const float* W3  = (const float*)d_in[10];
    const float* as3 = (const float*)d_in[11];
    const float* ad3 = (const float*)d_in[12];
    const float* b3  = (const float*)d_in[13];
    float* out = (float*)d_out;

    dim3 blk(256);
    dim3 gemm_g1((F1 + GBN - 1) / GBN,   (NN + GBM - 1) / GBM);
    dim3 gemm_g3((OUTC + GBN - 1) / GBN, (NN + GBM - 1) / GBM);
    int nbN    = (NN + 255) / 256;
    int nbE    = (EE + 255) / 256;
    int nbE2   = (E2V + 255) / 256;
    int nbNH   = (NN * 8 + 255) / 256;
    int nbWarp = (NN * 32 + 255) / 256;

    // ---- CSR build (also resets g_gmax) ----
    init_deg_k<<<nbN, blk>>>();
    count_k<<<nbE, blk>>>(dstv);
    scan1_k<<<NBLK, SB>>>();
    scan2_k<<<1, 128>>>();
    scan3_k<<<nbN, blk>>>();
    scatter_k<<<nbE2, blk>>>(srcv, dstv);

    // ---- layer 1: 128 -> 8x32 (fp32 A = x) ----
    tf32gemm_k<<<gemm_g1, blk>>>(x, W1, NN, F1, 128);
    dots_k<8><<<nbNH, blk>>>(as1, ad1, 32, 0);
    gat_fused8_k<<<nbWarp, blk>>>(b1, 1, 0);

    // ---- layer 2: 256 -> 8x32 (fp16 A = g_out16) ----
    tf32gemm_f16a_k<<<gemm_g1, blk>>>(W2, NN, F1, F1);
    dots_k<8><<<nbNH, blk>>>(as2, ad2, 32, 1);
    gat_fused8_k<<<nbWarp, blk>>>(b2, 1, 1);

    // ---- layer 3: 256 -> 40 + log_softmax (fp16 A) ----
    tf32gemm_f16a_k<<<gemm_g3, blk>>>(W3, NN, OUTC, F1);
    dots_k<1><<<nbN, blk>>>(as3, ad3, OUTC, 2);
    gat_fused1_k<<<nbWarp, blk>>>(b3, out, 2);
}

// round 16
// speedup vs baseline: 1.2467x; 1.2467x over previous
#include <cuda_runtime.h>
#include <cuda_fp16.h>
#include <math.h>
#include <stdint.h>

#define NN   50000
#define EE   800000
#define E2V  (EE + NN)
#define F1   256
#define OUTC 40
#define SB   512
#define NBLK ((NN + SB - 1) / SB)

// ---- scratch ----
__device__ __half g_h16  [(size_t)NN * F1];  // GEMM output / aggregation source (fp16)
__device__ __half g_out16[(size_t)NN * F1];  // aggregation output / next GEMM A (fp16)
__device__ float  g_asrc[NN * 8];
__device__ float  g_adst[NN * 8];
__device__ int    g_deg [NN];
__device__ int    g_rows[NN + 1];
__device__ int    g_cur [NN];
__device__ int    g_colsrc[E2V];
__device__ int    g_bsum[NBLK + 1];
__device__ float  g_gmax[3][16];

// ===========================================================================
__device__ __forceinline__ void atomicMaxF(float* addr, float val)
{
    unsigned int u = __float_as_uint(val);
    if (u >> 31) atomicMin((unsigned int*)addr, u);
    else         atomicMax((int*)addr, (int)u);
}

// ===========================================================================
// CSR build
// ===========================================================================
__global__ void init_deg_k()
{
    int i = blockIdx.x * blockDim.x + threadIdx.x;
    if (i < NN) g_deg[i] = 1;
    if (i < 48) ((float*)g_gmax)[i] = __int_as_float(0xFF800000);
}

__global__ void count_k(const int* __restrict__ dst)
{
    int e = blockIdx.x * blockDim.x + threadIdx.x;
    if (e < EE) atomicAdd(&g_deg[dst[e]], 1);
}

__global__ void scan1_k()
{
    __shared__ int sh[SB];
    int i = blockIdx.x * SB + threadIdx.x;
    sh[threadIdx.x] = (i < NN) ? g_deg[i] : 0;
    __syncthreads();
    #pragma unroll
    for (int o = 1; o < SB; o <<= 1) {
        int t = (threadIdx.x >= o) ? sh[threadIdx.x - o] : 0;
        __syncthreads();
        sh[threadIdx.x] += t;
        __syncthreads();
    }
    if (i < NN) g_rows[i + 1] = sh[threadIdx.x];
    if (threadIdx.x == SB - 1) g_bsum[blockIdx.x] = sh[SB - 1];
}

__global__ void scan2_k()
{
    __shared__ int sh[128];
    int t = threadIdx.x;
    int v = (t < NBLK) ? g_bsum[t] : 0;
    sh[t] = v;
    __syncthreads();
    #pragma unroll
    for (int o = 1; o < 128; o <<= 1) {
        int u = (t >= o) ? sh[t - o] : 0;
        __syncthreads();
        sh[t] += u;
        __syncthreads();
    }
    if (t < NBLK) g_bsum[t] = sh[t] - v;
}

__global__ void scan3_k()
{
    int i = blockIdx.x * blockDim.x + threadIdx.x;
    if (i >= NN) return;
    int end = g_rows[i + 1] + g_bsum[i / SB];
    g_rows[i + 1] = end;
    g_cur[i] = end - g_deg[i];
    if (i == 0) g_rows[0] = 0;
}

__global__ void scatter_k(const int* __restrict__ src, const int* __restrict__ dst)
{
    int e = blockIdx.x * blockDim.x + threadIdx.x;
    if (e >= E2V) return;
    int s, d;
    if (e < EE) { s = src[e]; d = dst[e]; } else { s = d = e - EE; }
    int pos = atomicAdd(&g_cur[d], 1);
    g_colsrc[pos] = s;
}

// ===========================================================================
// Layer-3 attention dots (1 head x 40 ch) + global max
// ===========================================================================
__global__ void __launch_bounds__(256) dots1_k(const float* __restrict__ att_s,
                                               const float* __restrict__ att_d,
                                               int layer)
{
    __shared__ float rs[256], rd[256];
    int tid = threadIdx.x;
    int i = blockIdx.x * blockDim.x + tid;
    float s = -INFINITY, d = -INFINITY;
    if (i < NN) {
        const __half2* hp = (const __half2*)(g_h16 + (size_t)i * OUTC);
        float ss = 0.f, dd = 0.f;
        for (int c = 0; c < OUTC / 2; c++) {
            float2 v = __half22float2(__ldg(&hp[c]));
            ss = fmaf(v.x, att_s[2 * c], ss);
            ss = fmaf(v.y, att_s[2 * c + 1], ss);
            dd = fmaf(v.x, att_d[2 * c], dd);
            dd = fmaf(v.y, att_d[2 * c + 1], dd);
        }
        g_asrc[i] = ss;
        g_adst[i] = dd;
        s = ss; d = dd;
    }
    rs[tid] = s; rd[tid] = d;
    __syncthreads();
    #pragma unroll
    for (int o = 128; o >= 1; o >>= 1) {
        if (tid < o) {
            rs[tid] = fmaxf(rs[tid], rs[tid + o]);
            rd[tid] = fmaxf(rd[tid], rd[tid + o]);
        }
        __syncthreads();
    }
    if (tid == 0) {
        atomicMaxF(&g_gmax[layer][0], rs[0]);
        atomicMaxF(&g_gmax[layer][8], rd[0]);
    }
}

// ===========================================================================
// SINGLE-PASS fused softmax + aggregation, 8 heads.
// Exp staging: lane = (eslot 0-3) x (head 0-7) as before.
// Aggregation: lane owns 8 CONSECUTIVE channels (lane*8..+7, head lane>>2)
//   -> ONE LDG.128 per lane per edge, one STG.128 at the end.
// ===========================================================================
__global__ void __launch_bounds__(256) gat_fused8_k(const float* __restrict__ bias,
                                                    int relu, int layer)
{
    __shared__ float sex[8][32];
    __shared__ int   ssrc[8][4];

    int w = (blockIdx.x * blockDim.x + threadIdx.x) >> 5;
    int lane = threadIdx.x & 31;
    int wl = (threadIdx.x >> 5);
    if (w >= NN) return;
    int d = w;
    int beg = g_rows[d], end = g_rows[d + 1];

    int hsel   = lane & 7;    // head this lane computes exp for
    int eslot  = lane >> 3;   // edge slot within chunk
    int myhead = lane >> 2;   // head of this lane's aggregation channels

    float adh = __ldg(&g_adst[d * 8 + hsel]);
    float bh  = g_gmax[layer][hsel] + g_gmax[layer][8 + hsel];
    float bndh = bh > 0.f ? bh : 0.2f * bh;

    float acc[8];
    #pragma unroll
    for (int k = 0; k < 8; k++) acc[k] = 0.f;
    float smpart = 0.f;

    int p0 = beg;
    int nfull = (end - beg) >> 2;
    for (int ch = 0; ch < nfull; ch++, p0 += 4) {
        int s = __ldg(&g_colsrc[p0 + eslot]);
        float e = __ldg(&g_asrc[s * 8 + hsel]) + adh;
        e = e > 0.f ? e : 0.2f * e;
        float ex = __expf(e - bndh);
        smpart += ex;
        sex[wl][lane] = ex;
        if (hsel == 0) ssrc[wl][eslot] = s;
        __syncwarp();
        #pragma unroll
        for (int e4 = 0; e4 < 4; e4++) {
            int se = ssrc[wl][e4];
            float wgt = sex[wl][e4 * 8 + myhead];
            uint4 v = __ldg((const uint4*)(g_h16 + (size_t)se * F1) + lane);
            float2 f0 = __half22float2(*(__half2*)&v.x);
            float2 f1 = __half22float2(*(__half2*)&v.y);
            float2 f2 = __half22float2(*(__half2*)&v.z);
            float2 f3 = __half22float2(*(__half2*)&v.w);
            acc[0] = fmaf(wgt, f0.x, acc[0]);
            acc[1] = fmaf(wgt, f0.y, acc[1]);
            acc[2] = fmaf(wgt, f1.x, acc[2]);
            acc[3] = fmaf(wgt, f1.y, acc[3]);
            acc[4] = fmaf(wgt, f2.x, acc[4]);
            acc[5] = fmaf(wgt, f2.y, acc[5]);
            acc[6] = fmaf(wgt, f3.x, acc[6]);
            acc[7] = fmaf(wgt, f3.y, acc[7]);
        }
        __syncwarp();
    }
    int rem = end - p0;
    if (rem > 0) {
        float ex = 0.f;
        int s = 0;
        if (eslot < rem) {
            s = __ldg(&g_colsrc[p0 + eslot]);
            float e = __ldg(&g_asrc[s * 8 + hsel]) + adh;
            e = e > 0.f ? e : 0.2f * e;
            ex = __expf(e - bndh);
            smpart += ex;
        }
        sex[wl][lane] = ex;
        if (hsel == 0 && eslot < rem) ssrc[wl][eslot] = s;
        __syncwarp();
        for (int e4 = 0; e4 < rem; e4++) {
            int se = ssrc[wl][e4];
            float wgt = sex[wl][e4 * 8 + myhead];
            uint4 v = __ldg((const uint4*)(g_h16 + (size_t)se * F1) + lane);
            float2 f0 = __half22float2(*(__half2*)&v.x);
            float2 f1 = __half22float2(*(__half2*)&v.y);
            float2 f2 = __half22float2(*(__half2*)&v.z);
            float2 f3 = __half22float2(*(__half2*)&v.w);
            acc[0] = fmaf(wgt, f0.x, acc[0]);
            acc[1] = fmaf(wgt, f0.y, acc[1]);
            acc[2] = fmaf(wgt, f1.x, acc[2]);
            acc[3] = fmaf(wgt, f1.y, acc[3]);
            acc[4] = fmaf(wgt, f2.x, acc[4]);
            acc[5] = fmaf(wgt, f2.y, acc[5]);
            acc[6] = fmaf(wgt, f3.x, acc[6]);
            acc[7] = fmaf(wgt, f3.y, acc[7]);
        }
        __syncwarp();
    }

    // per-head sums: lanes {h, h+8, h+16, h+24} hold partials of head h
    smpart += __shfl_xor_sync(0xffffffffu, smpart, 8);
    smpart += __shfl_xor_sync(0xffffffffu, smpart, 16);
    float invl = 1.f / (smpart + 1e-16f);        // lane holds inv of head lane&7
    float inv = __shfl_sync(0xffffffffu, invl, myhead);

    // bias for channels lane*8 .. lane*8+7
    const float4* bp = (const float4*)(bias + lane * 8);
    float4 b0 = __ldg(bp), b1 = __ldg(bp + 1);
    float v0 = acc[0] * inv + b0.x;
    float v1 = acc[1] * inv + b0.y;
    float v2 = acc[2] * inv + b0.z;
    float v3 = acc[3] * inv + b0.w;
    float v4 = acc[4] * inv + b1.x;
    float v5 = acc[5] * inv + b1.y;
    float v6 = acc[6] * inv + b1.z;
    float v7 = acc[7] * inv + b1.w;
    if (relu) {
        v0 = fmaxf(v0, 0.f); v1 = fmaxf(v1, 0.f); v2 = fmaxf(v2, 0.f); v3 = fmaxf(v3, 0.f);
        v4 = fmaxf(v4, 0.f); v5 = fmaxf(v5, 0.f); v6 = fmaxf(v6, 0.f); v7 = fmaxf(v7, 0.f);
    }
    __half2 h0 = __floats2half2_rn(v0, v1);
    __half2 h1 = __floats2half2_rn(v2, v3);
    __half2 h2 = __floats2half2_rn(v4, v5);
    __half2 h3 = __floats2half2_rn(v6, v7);
    uint4 o;
    o.x = *(uint32_t*)&h0; o.y = *(uint32_t*)&h1;
    o.z = *(uint32_t*)&h2; o.w = *(uint32_t*)&h3;
    ((uint4*)(g_out16 + (size_t)d * F1))[lane] = o;
}

// ===========================================================================
// SINGLE-PASS fused layer-3 (R9-proven)
// ===========================================================================
__global__ void __launch_bounds__(256) gat_fused1_k(const float* __restrict__ bias,
                                                    float* __restrict__ out, int layer)
{
    __shared__ float sex[8][32];
    __shared__ int   ssrc[8][32];

    int w = (blockIdx.x * blockDim.x + threadIdx.x) >> 5;
    int lane = threadIdx.x & 31;
    int wl = (threadIdx.x >> 5);
    if (w >= NN) return;
    int d = w;
    int beg = g_rows[d], end = g_rows[d + 1];
    float add = g_adst[d];
    float b = g_gmax[layer][0] + g_gmax[layer][8];
    float bnd = b > 0.f ? b : 0.2f * b;

    float a0 = 0.f, a1 = 0.f, smpart = 0.f;

    for (int p0 = beg; p0 < end; p0 += 32) {
        int ne = min(32, end - p0);
        float ex = 0.f;
        int s = 0;
        if (lane < ne) {
            s = __ldg(&g_colsrc[p0 + lane]);
            float e = __ldg(&g_asrc[s]) + add;
            e = e > 0.f ? e : 0.2f * e;
            ex = __expf(e - bnd);
            smpart += ex;
        }
        sex[wl][lane] = ex;
        ssrc[wl][lane] = s;
        __syncwarp();
        for (int e = 0; e < ne; e++) {
            int se = ssrc[wl][e];
            float al = sex[wl][e];
            const __half* hp = g_h16 + (size_t)se * OUTC;
            a0 = fmaf(al, __half2float(__ldg(&hp[lane])), a0);
            if (lane < 8) a1 = fmaf(al, __half2float(__ldg(&hp[lane + 32])), a1);
        }
        __syncwarp();
    }
    #pragma unroll
    for (int o = 16; o; o >>= 1) smpart += __shfl_xor_sync(0xffffffffu, smpart, o);
    float inv = 1.f / (smpart + 1e-16f);

    float v0 = a0 * inv + bias[lane];
    float v1 = (lane < 8) ? a1 * inv + bias[lane + 32] : -INFINITY;
    float m = fmaxf(v0, v1);
    #pragma unroll
    for (int o = 16; o; o >>= 1) m = fmaxf(m, __shfl_xor_sync(0xffffffffu, m, o));
    float s2 = __expf(v0 - m) + ((lane < 8) ? __expf(v1 - m) : 0.f);
    #pragma unroll
    for (int o = 16; o; o >>= 1) s2 += __shfl_xor_sync(0xffffffffu, s2, o);
    float lg = m + logf(s2);
    out[(size_t)d * OUTC + lane] = v0 - lg;
    if (lane < 8) out[(size_t)d * OUTC + lane + 32] = v1 - lg;
}

// ===========================================================================
// Common GEMM pieces
// ===========================================================================
#define GBM 128
#define GBN 64
#define GBK 16
#define AS_STRIDE 20
#define BS_STRIDE 72

__device__ __forceinline__ void cp16(uint32_t dst, const void* src, int valid)
{
    asm volatile("cp.async.ca.shared.global [%0], [%1], 16, %2;\n"
                 :: "r"(dst), "l"(src), "r"(valid ? 16 : 0));
}

__device__ __forceinline__ void mma1688(float* c, const uint32_t* a, const uint32_t* b)
{
    asm volatile(
        "mma.sync.aligned.m16n8k8.row.col.f32.tf32.tf32.f32 "
        "{%0,%1,%2,%3},{%4,%5,%6,%7},{%8,%9},{%0,%1,%2,%3};"
        : "+f"(c[0]), "+f"(c[1]), "+f"(c[2]), "+f"(c[3])
        : "r"(a[0]), "r"(a[1]), "r"(a[2]), "r"(a[3]), "r"(b[0]), "r"(b[1]));
}

// Fused-dots epilogue helper (layers 1-2: GBN=64 = 2 complete heads per block).
// Computes a_src/a_dst for this warp's head + rows and the global max bound.
__device__ __forceinline__ void epilogue_dots(
    const float c[2][4][4], const float* att_s, const float* att_d,
    int bm, int bn, int wm, int wn, int lr, int lc, int lane, int M, int layer)
{
    int hglob = (bn >> 5) + wn;
    const float* asp = att_s + hglob * 32;
    const float* adp = att_d + hglob * 32;
    float asv[4][2], adv[4][2];
    #pragma unroll
    for (int j = 0; j < 4; j++) {
        int chn = j * 8 + lc * 2;
        asv[j][0] = __ldg(&asp[chn]); asv[j][1] = __ldg(&asp[chn + 1]);
        adv[j][0] = __ldg(&adp[chn]); adv[j][1] = __ldg(&adp[chn + 1]);
    }
    float mxs = -INFINITY, mxd = -INFINITY;
    #pragma unroll
    for (int i = 0; i < 2; i++) {
        float sA = 0.f, dA = 0.f, sB = 0.f, dB = 0.f;
        #pragma unroll
        for (int j = 0; j < 4; j++) {
            sA = fmaf(c[i][j][0], asv[j][0], sA); sA = fmaf(c[i][j][1], asv[j][1], sA);
            dA = fmaf(c[i][j][0], adv[j][0], dA); dA = fmaf(c[i][j][1], adv[j][1], dA);
            sB = fmaf(c[i][j][2], asv[j][0], sB); sB = fmaf(c[i][j][3], asv[j][1], sB);
            dB = fmaf(c[i][j][2], adv[j][0], dB); dB = fmaf(c[i][j][3], adv[j][1], dB);
        }
        // quad reduce over lc (lane bits 0-1)
        sA += __shfl_xor_sync(0xffffffffu, sA, 1); sA += __shfl_xor_sync(0xffffffffu, sA, 2);
        dA += __shfl_xor_sync(0xffffffffu, dA, 1); dA += __shfl_xor_sync(0xffffffffu, dA, 2);
        sB += __shfl_xor_sync(0xffffffffu, sB, 1); sB += __shfl_xor_sync(0xffffffffu, sB, 2);
        dB += __shfl_xor_sync(0xffffffffu, dB, 1); dB += __shfl_xor_sync(0xffffffffu, dB, 2);
        int rA = bm + wm * 32 + i * 16 + lr;
        int rB = rA + 8;
        if (lc == 0) {
            if (rA < M) {
                g_asrc[rA * 8 + hglob] = sA;
                g_adst[rA * 8 + hglob] = dA;
                mxs = fmaxf(mxs, sA); mxd = fmaxf(mxd, dA);
            }
            if (rB < M) {
                g_asrc[rB * 8 + hglob] = sB;
                g_adst[rB * 8 + hglob] = dB;
                mxs = fmaxf(mxs, sB); mxd = fmaxf(mxd, dB);
            }
        }
    }
    #pragma unroll
    for (int o = 16; o; o >>= 1) {
        mxs = fmaxf(mxs, __shfl_xor_sync(0xffffffffu, mxs, o));
        mxd = fmaxf(mxd, __shfl_xor_sync(0xffffffffu, mxd, o));
    }
    if (lane == 0) {
        atomicMaxF(&g_gmax[layer][hglob], mxs);
        atomicMaxF(&g_gmax[layer][8 + hglob], mxd);
    }
}

// ===========================================================================
// TF32 GEMM, fp32 A (layer 1) with fused dots epilogue
// ===========================================================================
__global__ void __launch_bounds__(256) tf32gemm_k(const float* __restrict__ A,
                                                  const float* __restrict__ B,
                                                  const float* __restrict__ att_s,
                                                  const float* __restrict__ att_d,
                                                  int M, int Ncol, int K, int layer)
{
    __shared__ float As[2][GBM * AS_STRIDE];
    __shared__ float Bs[2][GBK * BS_STRIDE];

    int tid  = threadIdx.x;
    int warp = tid >> 5;
    int lane = tid & 31;
    int wm = warp >> 1;
    int wn = warp & 1;
    int bm = blockIdx.y * GBM;
    int bn = blockIdx.x * GBN;
    int lr = lane >> 2;
    int lc = lane & 3;

    int ar0 = tid >> 2;
    int ac  = (tid & 3) * 4;
    int br  = tid >> 4;
    int bc  = (tid & 15) * 4;

    uint32_t as_base = (uint32_t)__cvta_generic_to_shared(&As[0][0]);
    uint32_t bs_base = (uint32_t)__cvta_generic_to_shared(&Bs[0][0]);
    const uint32_t AS_BYTES = GBM * AS_STRIDE * 4;
    const uint32_t BS_BYTES = GBK * BS_STRIDE * 4;

    int niter = K / GBK;

    {
        #pragma unroll
        for (int i = 0; i < 2; i++) {
            int r = ar0 + i * 64;
            int gr = bm + r;
            int ok = gr < M;
            const float* src = A + (size_t)(ok ? gr : 0) * K + ac;
            cp16(as_base + (r * AS_STRIDE + ac) * 4, src, ok);
        }
        {
            int gc = bn + bc;
            int ok = gc < Ncol;
            const float* src = B + (size_t)br * Ncol + (ok ? gc : 0);
            cp16(bs_base + (br * BS_STRIDE + bc) * 4, src, ok);
        }
        asm volatile("cp.async.commit_group;\n" ::);
    }

    float c[2][4][4];
    #pragma unroll
    for (int i = 0; i < 2; i++)
        #pragma unroll
        for (int j = 0; j < 4; j++)
            #pragma unroll
            for (int r = 0; r < 4; r++) c[i][j][r] = 0.f;

    int buf = 0;
    for (int it = 0; it < niter; it++) {
        int has_next = (it + 1 < niter);
        if (has_next) {
            int k0 = (it + 1) * GBK;
            uint32_t ab = as_base + (buf ^ 1) * AS_BYTES;
            uint32_t bb = bs_base + (buf ^ 1) * BS_BYTES;
            #pragma unroll
            for (int i = 0; i < 2; i++) {
                int r = ar0 + i * 64;
                int gr = bm + r;
                int ok = gr < M;
                const float* src = A + (size_t)(ok ? gr : 0) * K + k0 + ac;
                cp16(ab + (r * AS_STRIDE + ac) * 4, src, ok);
            }
            {
                int gc = bn + bc;
                int ok = gc < Ncol;
                const float* src = B + (size_t)(k0 + br) * Ncol + (ok ? gc : 0);
                cp16(bb + (br * BS_STRIDE + bc) * 4, src, ok);
            }
            asm volatile("cp.async.commit_group;\n" ::);
            asm volatile("cp.async.wait_group 1;\n" ::);
        } else {
            asm volatile("cp.async.wait_group 0;\n" ::);
        }
        __syncthreads();

        const float* Asb = As[buf];
        const float* Bsb = Bs[buf];
        #pragma unroll
        for (int kk = 0; kk < GBK; kk += 8) {
            uint32_t afrag[2][4], bfrag[4][2];
            #pragma unroll
            for (int i = 0; i < 2; i++) {
                int rb = wm * 32 + i * 16;
                afrag[i][0] = __float_as_uint(Asb[(rb + lr)     * AS_STRIDE + kk + lc]);
                afrag[i][1] = __float_as_uint(Asb[(rb + 8 + lr) * AS_STRIDE + kk + lc]);
                afrag[i][2] = __float_as_uint(Asb[(rb + lr)     * AS_STRIDE + kk + 4 + lc]);
                afrag[i][3] = __float_as_uint(Asb[(rb + 8 + lr) * AS_STRIDE + kk + 4 + lc]);
            }
            #pragma unroll
            for (int j = 0; j < 4; j++) {
                int nb = wn * 32 + j * 8;
                bfrag[j][0] = __float_as_uint(Bsb[(kk + lc)     * BS_STRIDE + nb + lr]);
                bfrag[j][1] = __float_as_uint(Bsb[(kk + 4 + lc) * BS_STRIDE + nb + lr]);
            }
            #pragma unroll
            for (int i = 0; i < 2; i++)
                #pragma unroll
                for (int j = 0; j < 4; j++)
                    mma1688(c[i][j], afrag[i], bfrag[j]);
        }
        __syncthreads();
        buf ^= 1;
    }

    #pragma unroll
    for (int i = 0; i < 2; i++) {
        int r0 = bm + wm * 32 + i * 16 + lr;
        #pragma unroll
        for (int j = 0; j < 4; j++) {
            int col = bn + wn * 32 + j * 8 + lc * 2;
            if (col < Ncol) {
                if (r0 < M)
                    *(__half2*)&g_h16[(size_t)r0 * Ncol + col] =
                        __floats2half2_rn(c[i][j][0], c[i][j][1]);
                if (r0 + 8 < M)
                    *(__half2*)&g_h16[(size_t)(r0 + 8) * Ncol + col] =
                        __floats2half2_rn(c[i][j][2], c[i][j][3]);
            }
        }
    }
    epilogue_dots(c, att_s, att_d, bm, bn, wm, wn, lr, lc, lane, M, layer);
}

// ===========================================================================
// TF32 GEMM, fp16 A (layers 2-3). fuse_dots selects the dots epilogue.
// ===========================================================================
__global__ void __launch_bounds__(256) tf32gemm_f16a_k(const float* __restrict__ B,
                                                       const float* __restrict__ att_s,
                                                       const float* __restrict__ att_d,
                                                       int M, int Ncol, int K,
                                                       int layer, int fuse_dots)
{
    const __half* A = g_out16;
    __shared__ float As[2][GBM * AS_STRIDE];
    __shared__ float Bs[2][GBK * BS_STRIDE];

    int tid  = threadIdx.x;
    int warp = tid >> 5;
    int lane = tid & 31;
    int wm = warp >> 1;
    int wn = warp & 1;
    int bm = blockIdx.y * GBM;
    int bn = blockIdx.x * GBN;
    int lr = lane >> 2;
    int lc = lane & 3;

    int arow = tid >> 1;
    int ac8  = (tid & 1) * 8;
    int agr  = bm + arow;
    int aok  = agr < M;
    const __half* aptr = A + (size_t)(aok ? agr : 0) * K + ac8;

    int br  = tid >> 4;
    int bc  = (tid & 15) * 4;

    uint32_t bs_base = (uint32_t)__cvta_generic_to_shared(&Bs[0][0]);
    const uint32_t BS_BYTES = GBK * BS_STRIDE * 4;

    int niter = K / GBK;

    uint4 areg = aok ? __ldg((const uint4*)aptr) : make_uint4(0, 0, 0, 0);
    {
        int gc = bn + bc;
        int ok = gc < Ncol;
        const float* src = B + (size_t)br * Ncol + (ok ? gc : 0);
        cp16(bs_base + (br * BS_STRIDE + bc) * 4, src, ok);
        asm volatile("cp.async.commit_group;\n" ::);
    }

    float c[2][4][4];
    #pragma unroll
    for (int i = 0; i < 2; i++)
        #pragma unroll
        for (int j = 0; j < 4; j++)
            #pragma unroll
            for (int r = 0; r < 4; r++) c[i][j][r] = 0.f;

    int buf = 0;
    for (int it = 0; it < niter; it++) {
        {
            float2 f0 = __half22float2(*(__half2*)&areg.x);
            float2 f1 = __half22float2(*(__half2*)&areg.y);
            float2 f2 = __half22float2(*(__half2*)&areg.z);
            float2 f3 = __half22float2(*(__half2*)&areg.w);
            float* dst = &As[buf][arow * AS_STRIDE + ac8];
            *(float4*)dst       = make_float4(f0.x, f0.y, f1.x, f1.y);
            *(float4*)(dst + 4) = make_float4(f2.x, f2.y, f3.x, f3.y);
        }
        int has_next = (it + 1 < niter);
        if (has_next) {
            int k0 = (it + 1) * GBK;
            areg = aok ? __ldg((const uint4*)(aptr + k0)) : make_uint4(0, 0, 0, 0);
            uint32_t bb = bs_base + (buf ^ 1) * BS_BYTES;
            int gc = bn + bc;
            int ok = gc < Ncol;
            const float* src = B + (size_t)(k0 + br) * Ncol + (ok ? gc : 0);
            cp16(bb + (br * BS_STRIDE + bc) * 4, src, ok);
            asm volatile("cp.async.commit_group;\n" ::);
            asm volatile("cp.async.wait_group 1;\n" ::);
        } else {
            asm volatile("cp.async.wait_group 0;\n" ::);
        }
        __syncthreads();

        const float* Asb = As[buf];
        const float* Bsb = Bs[buf];
        #pragma unroll
        for (int kk = 0; kk < GBK; kk += 8) {
            uint32_t afrag[2][4], bfrag[4][2];
            #pragma unroll
            for (int i = 0; i < 2; i++) {
                int rb = wm * 32 + i * 16;
                afrag[i][0] = __float_as_uint(Asb[(rb + lr)     * AS_STRIDE + kk + lc]);
                afrag[i][1] = __float_as_uint(Asb[(rb + 8 + lr) * AS_STRIDE + kk + lc]);
                afrag[i][2] = __float_as_uint(Asb[(rb + lr)     * AS_STRIDE + kk + 4 + lc]);
                afrag[i][3] = __float_as_uint(Asb[(rb + 8 + lr) * AS_STRIDE + kk + 4 + lc]);
            }
            #pragma unroll
            for (int j = 0; j < 4; j++) {
                int nb = wn * 32 + j * 8;
                bfrag[j][0] = __float_as_uint(Bsb[(kk + lc)     * BS_STRIDE + nb + lr]);
                bfrag[j][1] = __float_as_uint(Bsb[(kk + 4 + lc) * BS_STRIDE + nb + lr]);
            }
            #pragma unroll
            for (int i = 0; i < 2; i++)
                #pragma unroll
                for (int j = 0; j < 4; j++)
                    mma1688(c[i][j], afrag[i], bfrag[j]);
        }
        __syncthreads();
        buf ^= 1;
    }

    #pragma unroll
    for (int i = 0; i < 2; i++) {
        int r0 = bm + wm * 32 + i * 16 + lr;
        #pragma unroll
        for (int j = 0; j < 4; j++) {
            int col = bn + wn * 32 + j * 8 + lc * 2;
            if (col < Ncol) {
                if (r0 < M)
                    *(__half2*)&g_h16[(size_t)r0 * Ncol + col] =
                        __floats2half2_rn(c[i][j][0], c[i][j][1]);
                if (r0 + 8 < M)
                    *(__half2*)&g_h16[(size_t)(r0 + 8) * Ncol + col] =
                        __floats2half2_rn(c[i][j][2], c[i][j][3]);
            }
        }
    }
    if (fuse_dots)
        epilogue_dots(c, att_s, att_d, bm, bn, wm, wn, lr, lc, lane, M, layer);
}

// ===========================================================================
// Launcher
// ===========================================================================
extern "C" void kernel_launch(void* const* d_in, const int* in_sizes, int n_in,
                              void* d_out, int out_size)
{
    const float* x    = (const float*)d_in[0];
    const int*   ei   = (const int*)  d_in[1];
    const int*   srcv = ei;
    const int*   dstv = ei + EE;
    const float* W1  = (const float*)d_in[2];
    const float* as1 = (const float*)d_in[3];
    const float* ad1 = (const float*)d_in[4];
    const float* b1  = (const float*)d_in[5];
    const float* W2  = (const float*)d_in[6];
    const float* as2 = (const float*)d_in[7];
    const float* ad2 = (const float*)d_in[8];
    const float* b2  = (const float*)d_in[9];
    const float* W3  = (const float*)d_in[10];
    const float* as3 = (const float*)d_in[11];
    const float* ad3 = (const float*)d_in[12];
    const float* b3  = (const float*)d_in[13];
    float* out = (float*)d_out;

    dim3 blk(256);
    dim3 gemm_g1((F1 + GBN - 1) / GBN,   (NN + GBM - 1) / GBM);
    dim3 gemm_g3((OUTC + GBN - 1) / GBN, (NN + GBM - 1) / GBM);
    int nbN    = (NN + 255) / 256;
    int nbE    = (EE + 255) / 256;
    int nbE2   = (E2V + 255) / 256;
    int nbWarp = (NN * 32 + 255) / 256;

    // ---- CSR build (also resets g_gmax; must precede GEMMs) ----
    init_deg_k<<<nbN, blk>>>();
    count_k<<<nbE, blk>>>(dstv);
    scan1_k<<<NBLK, SB>>>();
    scan2_k<<<1, 128>>>();
    scan3_k<<<nbN, blk>>>();
    scatter_k<<<nbE2, blk>>>(srcv, dstv);

    // ---- layer 1: 128 -> 8x32 (GEMM + fused dots) ----
    tf32gemm_k<<<gemm_g1, blk>>>(x, W1, as1, ad1, NN, F1, 128, 0);
    gat_fused8_k<<<nbWarp, blk>>>(b1, 1, 0);

    // ---- layer 2: 256 -> 8x32 (fp16-A GEMM + fused dots) ----
    tf32gemm_f16a_k<<<gemm_g1, blk>>>(W2, as2, ad2, NN, F1, F1, 1, 1);
    gat_fused8_k<<<nbWarp, blk>>>(b2, 1, 1);

    // ---- layer 3: 256 -> 40 + log_softmax ----
    tf32gemm_f16a_k<<<gemm_g3, blk>>>(W3, nullptr, nullptr, NN, OUTC, F1, 2, 0);
    dots1_k<<<nbN, blk>>>(as3, ad3, 2);
    gat_fused1_k<<<nbWarp, blk>>>(b3, out, 2);
}

// round 17
// speedup vs baseline: 1.2721x; 1.0204x over previous
#include <cuda_runtime.h>
#include <cuda_fp16.h>
#include <math.h>
#include <stdint.h>

#define NN   50000
#define EE   800000
#define E2V  (EE + NN)
#define F1   256
#define OUTC 40
#define SB   512
#define NBLK ((NN + SB - 1) / SB)

// ---- scratch ----
__device__ __half g_h16  [(size_t)NN * F1];  // GEMM output / aggregation source (fp16)
__device__ __half g_out16[(size_t)NN * F1];  // aggregation output / next GEMM A (fp16)
__device__ float  g_asrc[NN * 8];
__device__ float  g_adst[NN * 8];
__device__ int    g_deg [NN];
__device__ int    g_rows[NN + 1];
__device__ int    g_cur [NN];
__device__ int    g_colsrc[E2V];
__device__ int    g_bsum[NBLK + 1];
__device__ float  g_gmax[3][16];

// ===========================================================================
__device__ __forceinline__ void atomicMaxF(float* addr, float val)
{
    unsigned int u = __float_as_uint(val);
    if (u >> 31) atomicMin((unsigned int*)addr, u);
    else         atomicMax((int*)addr, (int)u);
}

// ===========================================================================
// CSR build
// ===========================================================================
__global__ void init_deg_k()
{
    int i = blockIdx.x * blockDim.x + threadIdx.x;
    if (i < NN) g_deg[i] = 1;
    if (i < 48) ((float*)g_gmax)[i] = __int_as_float(0xFF800000);
}

__global__ void count_k(const int* __restrict__ dst)
{
    int e = blockIdx.x * blockDim.x + threadIdx.x;
    if (e < EE) atomicAdd(&g_deg[dst[e]], 1);
}

__global__ void scan1_k()
{
    __shared__ int sh[SB];
    int i = blockIdx.x * SB + threadIdx.x;
    sh[threadIdx.x] = (i < NN) ? g_deg[i] : 0;
    __syncthreads();
    #pragma unroll
    for (int o = 1; o < SB; o <<= 1) {
        int t = (threadIdx.x >= o) ? sh[threadIdx.x - o] : 0;
        __syncthreads();
        sh[threadIdx.x] += t;
        __syncthreads();
    }
    if (i < NN) g_rows[i + 1] = sh[threadIdx.x];
    if (threadIdx.x == SB - 1) g_bsum[blockIdx.x] = sh[SB - 1];
}

__global__ void scan2_k()
{
    __shared__ int sh[128];
    int t = threadIdx.x;
    int v = (t < NBLK) ? g_bsum[t] : 0;
    sh[t] = v;
    __syncthreads();
    #pragma unroll
    for (int o = 1; o < 128; o <<= 1) {
        int u = (t >= o) ? sh[t - o] : 0;
        __syncthreads();
        sh[t] += u;
        __syncthreads();
    }
    if (t < NBLK) g_bsum[t] = sh[t] - v;
}

__global__ void scan3_k()
{
    int i = blockIdx.x * blockDim.x + threadIdx.x;
    if (i >= NN) return;
    int end = g_rows[i + 1] + g_bsum[i / SB];
    g_rows[i + 1] = end;
    g_cur[i] = end - g_deg[i];
    if (i == 0) g_rows[0] = 0;
}

__global__ void scatter_k(const int* __restrict__ src, const int* __restrict__ dst)
{
    int e = blockIdx.x * blockDim.x + threadIdx.x;
    if (e >= E2V) return;
    int s, d;
    if (e < EE) { s = src[e]; d = dst[e]; } else { s = d = e - EE; }
    int pos = atomicAdd(&g_cur[d], 1);
    g_colsrc[pos] = s;
}

// ===========================================================================
// Layer-3 attention dots (1 head x 40 ch) + global max
// ===========================================================================
__global__ void __launch_bounds__(256) dots1_k(const float* __restrict__ att_s,
                                               const float* __restrict__ att_d,
                                               int layer)
{
    __shared__ float rs[256], rd[256];
    int tid = threadIdx.x;
    int i = blockIdx.x * blockDim.x + tid;
    float s = -INFINITY, d = -INFINITY;
    if (i < NN) {
        const __half2* hp = (const __half2*)(g_h16 + (size_t)i * OUTC);
        float ss = 0.f, dd = 0.f;
        for (int c = 0; c < OUTC / 2; c++) {
            float2 v = __half22float2(__ldg(&hp[c]));
            ss = fmaf(v.x, att_s[2 * c], ss);
            ss = fmaf(v.y, att_s[2 * c + 1], ss);
            dd = fmaf(v.x, att_d[2 * c], dd);
            dd = fmaf(v.y, att_d[2 * c + 1], dd);
        }
        g_asrc[i] = ss;
        g_adst[i] = dd;
        s = ss; d = dd;
    }
    rs[tid] = s; rd[tid] = d;
    __syncthreads();
    #pragma unroll
    for (int o = 128; o >= 1; o >>= 1) {
        if (tid < o) {
            rs[tid] = fmaxf(rs[tid], rs[tid + o]);
            rd[tid] = fmaxf(rd[tid], rd[tid + o]);
        }
        __syncthreads();
    }
    if (tid == 0) {
        atomicMaxF(&g_gmax[layer][0], rs[0]);
        atomicMaxF(&g_gmax[layer][8], rd[0]);
    }
}

// ===========================================================================
// SINGLE-PASS fused softmax + aggregation, 8 heads. 8-EDGE CHUNKS:
// each lane computes exp for 2 (edge,head) pairs (eslot, eslot+4);
// aggregation = 8 back-to-back LDG.128 per chunk (MLP=8), 1 STG.128 at end.
// ===========================================================================
__global__ void __launch_bounds__(256) gat_fused8_k(const float* __restrict__ bias,
                                                    int relu, int layer)
{
    __shared__ float sex[8][64];
    __shared__ int   ssrc[8][8];

    int w = (blockIdx.x * blockDim.x + threadIdx.x) >> 5;
    int lane = threadIdx.x & 31;
    int wl = (threadIdx.x >> 5);
    if (w >= NN) return;
    int d = w;
    int beg = g_rows[d], end = g_rows[d + 1];

    int hsel   = lane & 7;    // head this lane computes exp for
    int eslot  = lane >> 3;   // first edge slot (0-3); second is eslot+4
    int myhead = lane >> 2;   // head of this lane's aggregation channels

    float adh = __ldg(&g_adst[d * 8 + hsel]);
    float bh  = g_gmax[layer][hsel] + g_gmax[layer][8 + hsel];
    float bndh = bh > 0.f ? bh : 0.2f * bh;

    float acc[8];
    #pragma unroll
    for (int k = 0; k < 8; k++) acc[k] = 0.f;
    float smpart = 0.f;

    int p0 = beg;
    int nfull = (end - beg) >> 3;
    for (int ch = 0; ch < nfull; ch++, p0 += 8) {
        int s0 = __ldg(&g_colsrc[p0 + eslot]);
        int s1 = __ldg(&g_colsrc[p0 + 4 + eslot]);
        float e0 = __ldg(&g_asrc[s0 * 8 + hsel]) + adh;
        float e1 = __ldg(&g_asrc[s1 * 8 + hsel]) + adh;
        e0 = e0 > 0.f ? e0 : 0.2f * e0;
        e1 = e1 > 0.f ? e1 : 0.2f * e1;
        float ex0 = __expf(e0 - bndh);
        float ex1 = __expf(e1 - bndh);
        smpart += ex0 + ex1;
        sex[wl][eslot * 8 + hsel]       = ex0;
        sex[wl][(eslot + 4) * 8 + hsel] = ex1;
        if (hsel == 0) { ssrc[wl][eslot] = s0; ssrc[wl][eslot + 4] = s1; }
        __syncwarp();
        #pragma unroll
        for (int e4 = 0; e4 < 8; e4++) {
            int se = ssrc[wl][e4];
            float wgt = sex[wl][e4 * 8 + myhead];
            uint4 v = __ldg((const uint4*)(g_h16 + (size_t)se * F1) + lane);
            float2 f0 = __half22float2(*(__half2*)&v.x);
            float2 f1 = __half22float2(*(__half2*)&v.y);
            float2 f2 = __half22float2(*(__half2*)&v.z);
            float2 f3 = __half22float2(*(__half2*)&v.w);
            acc[0] = fmaf(wgt, f0.x, acc[0]);
            acc[1] = fmaf(wgt, f0.y, acc[1]);
            acc[2] = fmaf(wgt, f1.x, acc[2]);
            acc[3] = fmaf(wgt, f1.y, acc[3]);
            acc[4] = fmaf(wgt, f2.x, acc[4]);
            acc[5] = fmaf(wgt, f2.y, acc[5]);
            acc[6] = fmaf(wgt, f3.x, acc[6]);
            acc[7] = fmaf(wgt, f3.y, acc[7]);
        }
        __syncwarp();
    }
    int rem = end - p0;
    if (rem > 0) {
        float ex0 = 0.f, ex1 = 0.f;
        int s0 = 0, s1 = 0;
        if (eslot < rem) {
            s0 = __ldg(&g_colsrc[p0 + eslot]);
            float e0 = __ldg(&g_asrc[s0 * 8 + hsel]) + adh;
            e0 = e0 > 0.f ? e0 : 0.2f * e0;
            ex0 = __expf(e0 - bndh);
            smpart += ex0;
        }
        if (eslot + 4 < rem) {
            s1 = __ldg(&g_colsrc[p0 + 4 + eslot]);
            float e1 = __ldg(&g_asrc[s1 * 8 + hsel]) + adh;
            e1 = e1 > 0.f ? e1 : 0.2f * e1;
            ex1 = __expf(e1 - bndh);
            smpart += ex1;
        }
        sex[wl][eslot * 8 + hsel]       = ex0;
        sex[wl][(eslot + 4) * 8 + hsel] = ex1;
        if (hsel == 0) {
            if (eslot < rem)     ssrc[wl][eslot] = s0;
            if (eslot + 4 < rem) ssrc[wl][eslot + 4] = s1;
        }
        __syncwarp();
        for (int e4 = 0; e4 < rem; e4++) {
            int se = ssrc[wl][e4];
            float wgt = sex[wl][e4 * 8 + myhead];
            uint4 v = __ldg((const uint4*)(g_h16 + (size_t)se * F1) + lane);
            float2 f0 = __half22float2(*(__half2*)&v.x);
            float2 f1 = __half22float2(*(__half2*)&v.y);
            float2 f2 = __half22float2(*(__half2*)&v.z);
            float2 f3 = __half22float2(*(__half2*)&v.w);
            acc[0] = fmaf(wgt, f0.x, acc[0]);
            acc[1] = fmaf(wgt, f0.y, acc[1]);
            acc[2] = fmaf(wgt, f1.x, acc[2]);
            acc[3] = fmaf(wgt, f1.y, acc[3]);
            acc[4] = fmaf(wgt, f2.x, acc[4]);
            acc[5] = fmaf(wgt, f2.y, acc[5]);
            acc[6] = fmaf(wgt, f3.x, acc[6]);
            acc[7] = fmaf(wgt, f3.y, acc[7]);
        }
        __syncwarp();
    }

    // per-head sums: lanes {h, h+8, h+16, h+24} hold partials of head h
    smpart += __shfl_xor_sync(0xffffffffu, smpart, 8);
    smpart += __shfl_xor_sync(0xffffffffu, smpart, 16);
    float invl = 1.f / (smpart + 1e-16f);        // lane holds inv of head lane&7
    float inv = __shfl_sync(0xffffffffu, invl, myhead);

    const float4* bp = (const float4*)(bias + lane * 8);
    float4 b0 = __ldg(bp), b1 = __ldg(bp + 1);
    float v0 = acc[0] * inv + b0.x;
    float v1 = acc[1] * inv + b0.y;
    float v2 = acc[2] * inv + b0.z;
    float v3 = acc[3] * inv + b0.w;
    float v4 = acc[4] * inv + b1.x;
    float v5 = acc[5] * inv + b1.y;
    float v6 = acc[6] * inv + b1.z;
    float v7 = acc[7] * inv + b1.w;
    if (relu) {
        v0 = fmaxf(v0, 0.f); v1 = fmaxf(v1, 0.f); v2 = fmaxf(v2, 0.f); v3 = fmaxf(v3, 0.f);
        v4 = fmaxf(v4, 0.f); v5 = fmaxf(v5, 0.f); v6 = fmaxf(v6, 0.f); v7 = fmaxf(v7, 0.f);
    }
    __half2 h0 = __floats2half2_rn(v0, v1);
    __half2 h1 = __floats2half2_rn(v2, v3);
    __half2 h2 = __floats2half2_rn(v4, v5);
    __half2 h3 = __floats2half2_rn(v6, v7);
    uint4 o;
    o.x = *(uint32_t*)&h0; o.y = *(uint32_t*)&h1;
    o.z = *(uint32_t*)&h2; o.w = *(uint32_t*)&h3;
    ((uint4*)(g_out16 + (size_t)d * F1))[lane] = o;
}

// ===========================================================================
// SINGLE-PASS fused layer-3 (R9-proven)
// ===========================================================================
__global__ void __launch_bounds__(256) gat_fused1_k(const float* __restrict__ bias,
                                                    float* __restrict__ out, int layer)
{
    __shared__ float sex[8][32];
    __shared__ int   ssrc[8][32];

    int w = (blockIdx.x * blockDim.x + threadIdx.x) >> 5;
    int lane = threadIdx.x & 31;
    int wl = (threadIdx.x >> 5);
    if (w >= NN) return;
    int d = w;
    int beg = g_rows[d], end = g_rows[d + 1];
    float add = g_adst[d];
    float b = g_gmax[layer][0] + g_gmax[layer][8];
    float bnd = b > 0.f ? b : 0.2f * b;

    float a0 = 0.f, a1 = 0.f, smpart = 0.f;

    for (int p0 = beg; p0 < end; p0 += 32) {
        int ne = min(32, end - p0);
        float ex = 0.f;
        int s = 0;
        if (lane < ne) {
            s = __ldg(&g_colsrc[p0 + lane]);
            float e = __ldg(&g_asrc[s]) + add;
            e = e > 0.f ? e : 0.2f * e;
            ex = __expf(e - bnd);
            smpart += ex;
        }
        sex[wl][lane] = ex;
        ssrc[wl][lane] = s;
        __syncwarp();
        for (int e = 0; e < ne; e++) {
            int se = ssrc[wl][e];
            float al = sex[wl][e];
            const __half* hp = g_h16 + (size_t)se * OUTC;
            a0 = fmaf(al, __half2float(__ldg(&hp[lane])), a0);
            if (lane < 8) a1 = fmaf(al, __half2float(__ldg(&hp[lane + 32])), a1);
        }
        __syncwarp();
    }
    #pragma unroll
    for (int o = 16; o; o >>= 1) smpart += __shfl_xor_sync(0xffffffffu, smpart, o);
    float inv = 1.f / (smpart + 1e-16f);

    float v0 = a0 * inv + bias[lane];
    float v1 = (lane < 8) ? a1 * inv + bias[lane + 32] : -INFINITY;
    float m = fmaxf(v0, v1);
    #pragma unroll
    for (int o = 16; o; o >>= 1) m = fmaxf(m, __shfl_xor_sync(0xffffffffu, m, o));
    float s2 = __expf(v0 - m) + ((lane < 8) ? __expf(v1 - m) : 0.f);
    #pragma unroll
    for (int o = 16; o; o >>= 1) s2 += __shfl_xor_sync(0xffffffffu, s2, o);
    float lg = m + logf(s2);
    out[(size_t)d * OUTC + lane] = v0 - lg;
    if (lane < 8) out[(size_t)d * OUTC + lane + 32] = v1 - lg;
}

// ===========================================================================
// Common GEMM pieces
// ===========================================================================
#define GBM 128
#define GBN 64
#define GBK 16
#define AS_STRIDE 20
#define BS_STRIDE 72

__device__ __forceinline__ void cp16(uint32_t dst, const void* src, int valid)
{
    asm volatile("cp.async.ca.shared.global [%0], [%1], 16, %2;\n"
                 :: "r"(dst), "l"(src), "r"(valid ? 16 : 0));
}

__device__ __forceinline__ void mma1688(float* c, const uint32_t* a, const uint32_t* b)
{
    asm volatile(
        "mma.sync.aligned.m16n8k8.row.col.f32.tf32.tf32.f32 "
        "{%0,%1,%2,%3},{%4,%5,%6,%7},{%8,%9},{%0,%1,%2,%3};"
        : "+f"(c[0]), "+f"(c[1]), "+f"(c[2]), "+f"(c[3])
        : "r"(a[0]), "r"(a[1]), "r"(a[2]), "r"(a[3]), "r"(b[0]), "r"(b[1]));
}

// Fused-dots epilogue helper (layers 1-2: GBN=64 = 2 complete heads per block).
__device__ __forceinline__ void epilogue_dots(
    const float c[2][4][4], const float* att_s, const float* att_d,
    int bm, int bn, int wm, int wn, int lr, int lc, int lane, int M, int layer)
{
    int hglob = (bn >> 5) + wn;
    const float* asp = att_s + hglob * 32;
    const float* adp = att_d + hglob * 32;
    float asv[4][2], adv[4][2];
    #pragma unroll
    for (int j = 0; j < 4; j++) {
        int chn = j * 8 + lc * 2;
        asv[j][0] = __ldg(&asp[chn]); asv[j][1] = __ldg(&asp[chn + 1]);
        adv[j][0] = __ldg(&adp[chn]); adv[j][1] = __ldg(&adp[chn + 1]);
    }
    float mxs = -INFINITY, mxd = -INFINITY;
    #pragma unroll
    for (int i = 0; i < 2; i++) {
        float sA = 0.f, dA = 0.f, sB = 0.f, dB = 0.f;
        #pragma unroll
        for (int j = 0; j < 4; j++) {
            sA = fmaf(c[i][j][0], asv[j][0], sA); sA = fmaf(c[i][j][1], asv[j][1], sA);
            dA = fmaf(c[i][j][0], adv[j][0], dA); dA = fmaf(c[i][j][1], adv[j][1], dA);
            sB = fmaf(c[i][j][2], asv[j][0], sB); sB = fmaf(c[i][j][3], asv[j][1], sB);
            dB = fmaf(c[i][j][2], adv[j][0], dB); dB = fmaf(c[i][j][3], adv[j][1], dB);
        }
        sA += __shfl_xor_sync(0xffffffffu, sA, 1); sA += __shfl_xor_sync(0xffffffffu, sA, 2);
        dA += __shfl_xor_sync(0xffffffffu, dA, 1); dA += __shfl_xor_sync(0xffffffffu, dA, 2);
        sB += __shfl_xor_sync(0xffffffffu, sB, 1); sB += __shfl_xor_sync(0xffffffffu, sB, 2);
        dB += __shfl_xor_sync(0xffffffffu, dB, 1); dB += __shfl_xor_sync(0xffffffffu, dB, 2);
        int rA = bm + wm * 32 + i * 16 + lr;
        int rB = rA + 8;
        if (lc == 0) {
            if (rA < M) {
                g_asrc[rA * 8 + hglob] = sA;
                g_adst[rA * 8 + hglob] = dA;
                mxs = fmaxf(mxs, sA); mxd = fmaxf(mxd, dA);
            }
            if (rB < M) {
                g_asrc[rB * 8 + hglob] = sB;
                g_adst[rB * 8 + hglob] = dB;
                mxs = fmaxf(mxs, sB); mxd = fmaxf(mxd, dB);
            }
        }
    }
    #pragma unroll
    for (int o = 16; o; o >>= 1) {
        mxs = fmaxf(mxs, __shfl_xor_sync(0xffffffffu, mxs, o));
        mxd = fmaxf(mxd, __shfl_xor_sync(0xffffffffu, mxd, o));
    }
    if (lane == 0) {
        atomicMaxF(&g_gmax[layer][hglob], mxs);
        atomicMaxF(&g_gmax[layer][8 + hglob], mxd);
    }
}

// ===========================================================================
// TF32 GEMM, fp32 A (layer 1) with fused dots epilogue
// ===========================================================================
__global__ void __launch_bounds__(256) tf32gemm_k(const float* __restrict__ A,
                                                  const float* __restrict__ B,
                                                  const float* __restrict__ att_s,
                                                  const float* __restrict__ att_d,
                                                  int M, int Ncol, int K, int layer)
{
    __shared__ float As[2][GBM * AS_STRIDE];
    __shared__ float Bs[2][GBK * BS_STRIDE];

    int tid  = threadIdx.x;
    int warp = tid >> 5;
    int lane = tid & 31;
    int wm = warp >> 1;
    int wn = warp & 1;
    int bm = blockIdx.y * GBM;
    int bn = blockIdx.x * GBN;
    int lr = lane >> 2;
    int lc = lane & 3;

    int ar0 = tid >> 2;
    int ac  = (tid & 3) * 4;
    int br  = tid >> 4;
    int bc  = (tid & 15) * 4;

    uint32_t as_base = (uint32_t)__cvta_generic_to_shared(&As[0][0]);
    uint32_t bs_base = (uint32_t)__cvta_generic_to_shared(&Bs[0][0]);
    const uint32_t AS_BYTES = GBM * AS_STRIDE * 4;
    const uint32_t BS_BYTES = GBK * BS_STRIDE * 4;

    int niter = K / GBK;

    {
        #pragma unroll
        for (int i = 0; i < 2; i++) {
            int r = ar0 + i * 64;
            int gr = bm + r;
            int ok = gr < M;
            const float* src = A + (size_t)(ok ? gr : 0) * K + ac;
            cp16(as_base + (r * AS_STRIDE + ac) * 4, src, ok);
        }
        {
            int gc = bn + bc;
            int ok = gc < Ncol;
            const float* src = B + (size_t)br * Ncol + (ok ? gc : 0);
            cp16(bs_base + (br * BS_STRIDE + bc) * 4, src, ok);
        }
        asm volatile("cp.async.commit_group;\n" ::);
    }

    float c[2][4][4];
    #pragma unroll
    for (int i = 0; i < 2; i++)
        #pragma unroll
        for (int j = 0; j < 4; j++)
            #pragma unroll
            for (int r = 0; r < 4; r++) c[i][j][r] = 0.f;

    int buf = 0;
    for (int it = 0; it < niter; it++) {
        int has_next = (it + 1 < niter);
        if (has_next) {
            int k0 = (it + 1) * GBK;
            uint32_t ab = as_base + (buf ^ 1) * AS_BYTES;
            uint32_t bb = bs_base + (buf ^ 1) * BS_BYTES;
            #pragma unroll
            for (int i = 0; i < 2; i++) {
                int r = ar0 + i * 64;
                int gr = bm + r;
                int ok = gr < M;
                const float* src = A + (size_t)(ok ? gr : 0) * K + k0 + ac;
                cp16(ab + (r * AS_STRIDE + ac) * 4, src, ok);
            }
            {
                int gc = bn + bc;
                int ok = gc < Ncol;
                const float* src = B + (size_t)(k0 + br) * Ncol + (ok ? gc : 0);
                cp16(bb + (br * BS_STRIDE + bc) * 4, src, ok);
            }
            asm volatile("cp.async.commit_group;\n" ::);
            asm volatile("cp.async.wait_group 1;\n" ::);
        } else {
            asm volatile("cp.async.wait_group 0;\n" ::);
        }
        __syncthreads();

        const float* Asb = As[buf];
        const float* Bsb = Bs[buf];
        #pragma unroll
        for (int kk = 0; kk < GBK; kk += 8) {
            uint32_t afrag[2][4], bfrag[4][2];
            #pragma unroll
            for (int i = 0; i < 2; i++) {
                int rb = wm * 32 + i * 16;
                afrag[i][0] = __float_as_uint(Asb[(rb + lr)     * AS_STRIDE + kk + lc]);
                afrag[i][1] = __float_as_uint(Asb[(rb + 8 + lr) * AS_STRIDE + kk + lc]);
                afrag[i][2] = __float_as_uint(Asb[(rb + lr)     * AS_STRIDE + kk + 4 + lc]);
                afrag[i][3] = __float_as_uint(Asb[(rb + 8 + lr) * AS_STRIDE + kk + 4 + lc]);
            }
            #pragma unroll
            for (int j = 0; j < 4; j++) {
                int nb = wn * 32 + j * 8;
                bfrag[j][0] = __float_as_uint(Bsb[(kk + lc)     * BS_STRIDE + nb + lr]);
                bfrag[j][1] = __float_as_uint(Bsb[(kk + 4 + lc) * BS_STRIDE + nb + lr]);
            }
            #pragma unroll
            for (int i = 0; i < 2; i++)
                #pragma unroll
                for (int j = 0; j < 4; j++)
                    mma1688(c[i][j], afrag[i], bfrag[j]);
        }
        __syncthreads();
        buf ^= 1;
    }

    #pragma unroll
    for (int i = 0; i < 2; i++) {
        int r0 = bm + wm * 32 + i * 16 + lr;
        #pragma unroll
        for (int j = 0; j < 4; j++) {
            int col = bn + wn * 32 + j * 8 + lc * 2;
            if (col < Ncol) {
                if (r0 < M)
                    *(__half2*)&g_h16[(size_t)r0 * Ncol + col] =
                        __floats2half2_rn(c[i][j][0], c[i][j][1]);
                if (r0 + 8 < M)
                    *(__half2*)&g_h16[(size_t)(r0 + 8) * Ncol + col] =
                        __floats2half2_rn(c[i][j][2], c[i][j][3]);
            }
        }
    }
    epilogue_dots(c, att_s, att_d, bm, bn, wm, wn, lr, lc, lane, M, layer);
}

// ===========================================================================
// TF32 GEMM, fp16 A (layers 2-3). fuse_dots selects the dots epilogue.
// ===========================================================================
__global__ void __launch_bounds__(256) tf32gemm_f16a_k(const float* __restrict__ B,
                                                       const float* __restrict__ att_s,
                                                       const float* __restrict__ att_d,
                                                       int M, int Ncol, int K,
                                                       int layer, int fuse_dots)
{
    const __half* A = g_out16;
    __shared__ float As[2][GBM * AS_STRIDE];
    __shared__ float Bs[2][GBK * BS_STRIDE];

    int tid  = threadIdx.x;
    int warp = tid >> 5;
    int lane = tid & 31;
    int wm = warp >> 1;
    int wn = warp & 1;
    int bm = blockIdx.y * GBM;
    int bn = blockIdx.x * GBN;
    int lr = lane >> 2;
    int lc = lane & 3;

    int arow = tid >> 1;
    int ac8  = (tid & 1) * 8;
    int agr  = bm + arow;
    int aok  = agr < M;
    const __half* aptr = A + (size_t)(aok ? agr : 0) * K + ac8;

    int br  = tid >> 4;
    int bc  = (tid & 15) * 4;

    uint32_t bs_base = (uint32_t)__cvta_generic_to_shared(&Bs[0][0]);
    const uint32_t BS_BYTES = GBK * BS_STRIDE * 4;

    int niter = K / GBK;

    uint4 areg = aok ? __ldg((const uint4*)aptr) : make_uint4(0, 0, 0, 0);
    {
        int gc = bn + bc;
        int ok = gc < Ncol;
        const float* src = B + (size_t)br * Ncol + (ok ? gc : 0);
        cp16(bs_base + (br * BS_STRIDE + bc) * 4, src, ok);
        asm volatile("cp.async.commit_group;\n" ::);
    }

    float c[2][4][4];
    #pragma unroll
    for (int i = 0; i < 2; i++)
        #pragma unroll
        for (int j = 0; j < 4; j++)
            #pragma unroll
            for (int r = 0; r < 4; r++) c[i][j][r] = 0.f;

    int buf = 0;
    for (int it = 0; it < niter; it++) {
        {
            float2 f0 = __half22float2(*(__half2*)&areg.x);
            float2 f1 = __half22float2(*(__half2*)&areg.y);
            float2 f2 = __half22float2(*(__half2*)&areg.z);
            float2 f3 = __half22float2(*(__half2*)&areg.w);
            float* dst = &As[buf][arow * AS_STRIDE + ac8];
            *(float4*)dst       = make_float4(f0.x, f0.y, f1.x, f1.y);
            *(float4*)(dst + 4) = make_float4(f2.x, f2.y, f3.x, f3.y);
        }
        int has_next = (it + 1 < niter);
        if (has_next) {
            int k0 = (it + 1) * GBK;
            areg = aok ? __ldg((const uint4*)(aptr + k0)) : make_uint4(0, 0, 0, 0);
            uint32_t bb = bs_base + (buf ^ 1) * BS_BYTES;
            int gc = bn + bc;
            int ok = gc < Ncol;
            const float* src = B + (size_t)(k0 + br) * Ncol + (ok ? gc : 0);
            cp16(bb + (br * BS_STRIDE + bc) * 4, src, ok);
            asm volatile("cp.async.commit_group;\n" ::);
            asm volatile("cp.async.wait_group 1;\n" ::);
        } else {
            asm volatile("cp.async.wait_group 0;\n" ::);
        }
        __syncthreads();

        const float* Asb = As[buf];
        const float* Bsb = Bs[buf];
        #pragma unroll
        for (int kk = 0; kk < GBK; kk += 8) {
            uint32_t afrag[2][4], bfrag[4][2];
            #pragma unroll
            for (int i = 0; i < 2; i++) {
                int rb = wm * 32 + i * 16;
                afrag[i][0] = __float_as_uint(Asb[(rb + lr)     * AS_STRIDE + kk + lc]);
                afrag[i][1] = __float_as_uint(Asb[(rb + 8 + lr) * AS_STRIDE + kk + lc]);
                afrag[i][2] = __float_as_uint(Asb[(rb + lr)     * AS_STRIDE + kk + 4 + lc]);
                afrag[i][3] = __float_as_uint(Asb[(rb + 8 + lr) * AS_STRIDE + kk + 4 + lc]);
            }
            #pragma unroll
            for (int j = 0; j < 4; j++) {
                int nb = wn * 32 + j * 8;
                bfrag[j][0] = __float_as_uint(Bsb[(kk + lc)     * BS_STRIDE + nb + lr]);
                bfrag[j][1] = __float_as_uint(Bsb[(kk + 4 + lc) * BS_STRIDE + nb + lr]);
            }
            #pragma unroll
            for (int i = 0; i < 2; i++)
                #pragma unroll
                for (int j = 0; j < 4; j++)
                    mma1688(c[i][j], afrag[i], bfrag[j]);
        }
        __syncthreads();
        buf ^= 1;
    }

    #pragma unroll
    for (int i = 0; i < 2; i++) {
        int r0 = bm + wm * 32 + i * 16 + lr;
        #pragma unroll
        for (int j = 0; j < 4; j++) {
            int col = bn + wn * 32 + j * 8 + lc * 2;
            if (col < Ncol) {
                if (r0 < M)
                    *(__half2*)&g_h16[(size_t)r0 * Ncol + col] =
                        __floats2half2_rn(c[i][j][0], c[i][j][1]);
                if (r0 + 8 < M)
                    *(__half2*)&g_h16[(size_t)(r0 + 8) * Ncol + col] =
                        __floats2half2_rn(c[i][j][2], c[i][j][3]);
            }
        }
    }
    if (fuse_dots)
        epilogue_dots(c, att_s, att_d, bm, bn, wm, wn, lr, lc, lane, M, layer);
}

// ===========================================================================
// Launcher
// ===========================================================================
extern "C" void kernel_launch(void* const* d_in, const int* in_sizes, int n_in,
                              void* d_out, int out_size)
{
    const float* x    = (const float*)d_in[0];
    const int*   ei   = (const int*)  d_in[1];
    const int*   srcv = ei;
    const int*   dstv = ei + EE;
    const float* W1  = (const float*)d_in[2];
    const float* as1 = (const float*)d_in[3];
    const float* ad1 = (const float*)d_in[4];
    const float* b1  = (const float*)d_in[5];
    const float* W2  = (const float*)d_in[6];
    const float* as2 = (const float*)d_in[7];
    const float* ad2 = (const float*)d_in[8];
    const float* b2  = (const float*)d_in[9];
    const float* W3  = (const float*)d_in[10];
    const float* as3 = (const float*)d_in[11];
    const float* ad3 = (const float*)d_in[12];
    const float* b3  = (const float*)d_in[13];
    float* out = (float*)d_out;

    dim3 blk(256);
    dim3 gemm_g1((F1 + GBN - 1) / GBN,   (NN + GBM - 1) / GBM);
    dim3 gemm_g3((OUTC + GBN - 1) / GBN, (NN + GBM - 1) / GBM);
    int nbN    = (NN + 255) / 256;
    int nbE    = (EE + 255) / 256;
    int nbE2   = (E2V + 255) / 256;
    int nbWarp = (NN * 32 + 255) / 256;

    // ---- CSR build (also resets g_gmax; must precede GEMMs) ----
    init_deg_k<<<nbN, blk>>>();
    count_k<<<nbE, blk>>>(dstv);
    scan1_k<<<NBLK, SB>>>();
    scan2_k<<<1, 128>>>();
    scan3_k<<<nbN, blk>>>();
    scatter_k<<<nbE2, blk>>>(srcv, dstv);

    // ---- layer 1: 128 -> 8x32 (GEMM + fused dots) ----
    tf32gemm_k<<<gemm_g1, blk>>>(x, W1, as1, ad1, NN, F1, 128, 0);
    gat_fused8_k<<<nbWarp, blk>>>(b1, 1, 0);

    // ---- layer 2: 256 -> 8x32 (fp16-A GEMM + fused dots) ----
    tf32gemm_f16a_k<<<gemm_g1, blk>>>(W2, as2, ad2, NN, F1, F1, 1, 1);
    gat_fused8_k<<<nbWarp, blk>>>(b2, 1, 1);

    // ---- layer 3: 256 -> 40 + log_softmax ----
    tf32gemm_f16a_k<<<gemm_g3, blk>>>(W3, nullptr, nullptr, NN, OUTC, F1, 2, 0);
    dots1_k<<<nbN, blk>>>(as3, ad3, 2);
    gat_fused1_k<<<nbWarp, blk>>>(b3, out, 2);
}